// round 1
// baseline (speedup 1.0000x reference)
#include <cuda_runtime.h>
#include <cuda_bf16.h>
#include <mma.h>
#include <cstdint>
#include <cstddef>

using namespace nvcuda;

// ---------------------------------------------------------------------------
// Problem dims (fixed by the reference)
// ---------------------------------------------------------------------------
#define NTOK   65536          // B*H*W = 16*64*64
#define CDIM   384
#define QKVN   1152           // 3*NH*DH
#define DFFN   1536
#define NHEAD  12
#define DHEAD  32
#define NWIN   1024           // B * 8 * 8

// ---------------------------------------------------------------------------
// Scratch (static device globals -- no allocation allowed)
// ---------------------------------------------------------------------------
__device__ __align__(256) float g_qkv [(size_t)NTOK * QKVN];   // 302 MB, window-row order
__device__ __align__(256) float g_attn[(size_t)NTOK * CDIM];   // window-row order
__device__ __align__(256) float g_proj[(size_t)NTOK * CDIM];   // window-row order
__device__ __align__(256) float g_y   [(size_t)NTOK * CDIM];   // token order (post attn residual)
__device__ __align__(256) float g_h   [(size_t)NTOK * DFFN];   // 402 MB FFN hidden
__device__ __align__(256) float g_f   [(size_t)NTOK * CDIM];   // FFN out (pre-LN)

// ---------------------------------------------------------------------------
// TF32 wmma GEMM, C = A @ B   (row-major everything), fp32 accumulate.
// Block tile 64x64, K-tile 32. 8 warps: 4 (M) x 2 (N), each warp 16x32.
// SHIFT_A: A rows are window-ordered tokens of shift2d(x) gathered on the fly.
// GELU:    exact gelu applied to accumulators before store.
// ---------------------------------------------------------------------------
constexpr int BM = 64, BN = 64, BK = 32;
constexpr int ALD = BK + 4;   // 36 (16B-aligned rows)
constexpr int BLD = BN + 4;   // 68

__device__ __forceinline__ float gelu_exact(float v) {
    return 0.5f * v * (1.0f + erff(v * 0.7071067811865475f));
}

template<bool SHIFT_A, bool GELU>
__global__ __launch_bounds__(256)
void gemm_tf32(const float* __restrict__ A, const float* __restrict__ B,
               float* __restrict__ C, int M, int N, int K)
{
    __shared__ float As[BM * ALD];
    __shared__ float Bs[BK * BLD];

    const int bm   = blockIdx.y * BM;
    const int bn   = blockIdx.x * BN;
    const int tid  = threadIdx.x;
    const int warp = tid >> 5;
    const int wm   = (warp & 3) * 16;
    const int wn   = (warp >> 2) * 32;

    wmma::fragment<wmma::accumulator, 16, 16, 8, float> acc0, acc1;
    wmma::fill_fragment(acc0, 0.0f);
    wmma::fill_fragment(acc1, 0.0f);

    // A loader: 8 contiguous k per thread; 4 threads per row
    const int a_row = tid >> 2;
    const int a_col = (tid & 3) * 8;
    // B loader: 8 contiguous n per thread; 8 threads per row
    const int b_row = tid >> 3;
    const int b_col = (tid & 7) * 8;

    // shift2d gather metadata for this thread's A row (window-ordered token)
    int bb = 0, hy = 0, wx = 0;
    if (SHIFT_A) {
        const int grow = bm + a_row;
        const int win  = grow >> 6;
        const int t    = grow & 63;
        bb = win >> 6;
        hy = ((win >> 3) & 7) * 8 + (t >> 3);
        wx = (win & 7) * 8 + (t & 7);
    }

    for (int kt = 0; kt < K; kt += BK) {
        float4 av0, av1;
        if (SHIFT_A) {
            // channel quarter boundaries (96) are multiples of 8, so this
            // 8-wide chunk has exactly one shifted source row.
            const int kk  = kt + a_col;
            const int qtr = kk / 96;
            int sh = hy, sw = wx;
            bool valid;
            if      (qtr == 0) { sh = hy - 1; valid = (sh >= 0); }
            else if (qtr == 1) { sh = hy + 1; valid = (sh < 64); }
            else if (qtr == 2) { sw = wx - 1; valid = (sw >= 0); }
            else               { sw = wx + 1; valid = (sw < 64); }
            if (valid) {
                const float* sp = A + (size_t)((bb * 64 + sh) * 64 + sw) * CDIM + kk;
                av0 = *(const float4*)(sp);
                av1 = *(const float4*)(sp + 4);
            } else {
                av0 = make_float4(0.f, 0.f, 0.f, 0.f);
                av1 = av0;
            }
        } else {
            const float* ap = A + (size_t)(bm + a_row) * K + kt + a_col;
            av0 = *(const float4*)(ap);
            av1 = *(const float4*)(ap + 4);
        }
        *(float4*)&As[a_row * ALD + a_col]     = av0;
        *(float4*)&As[a_row * ALD + a_col + 4] = av1;

        const float* bp = B + (size_t)(kt + b_row) * N + bn + b_col;
        float4 bv0 = *(const float4*)(bp);
        float4 bv1 = *(const float4*)(bp + 4);
        *(float4*)&Bs[b_row * BLD + b_col]     = bv0;
        *(float4*)&Bs[b_row * BLD + b_col + 4] = bv1;

        __syncthreads();

        #pragma unroll
        for (int ks = 0; ks < BK; ks += 8) {
            wmma::fragment<wmma::matrix_a, 16, 16, 8, wmma::precision::tf32, wmma::row_major> af;
            wmma::load_matrix_sync(af, &As[wm * ALD + ks], ALD);
            #pragma unroll
            for (int i = 0; i < af.num_elements; i++) af.x[i] = wmma::__float_to_tf32(af.x[i]);

            wmma::fragment<wmma::matrix_b, 16, 16, 8, wmma::precision::tf32, wmma::row_major> bf0, bf1;
            wmma::load_matrix_sync(bf0, &Bs[ks * BLD + wn], BLD);
            wmma::load_matrix_sync(bf1, &Bs[ks * BLD + wn + 16], BLD);
            #pragma unroll
            for (int i = 0; i < bf0.num_elements; i++) bf0.x[i] = wmma::__float_to_tf32(bf0.x[i]);
            #pragma unroll
            for (int i = 0; i < bf1.num_elements; i++) bf1.x[i] = wmma::__float_to_tf32(bf1.x[i]);

            wmma::mma_sync(acc0, af, bf0, acc0);
            wmma::mma_sync(acc1, af, bf1, acc1);
        }
        __syncthreads();
    }

    if (GELU) {
        #pragma unroll
        for (int i = 0; i < acc0.num_elements; i++) acc0.x[i] = gelu_exact(acc0.x[i]);
        #pragma unroll
        for (int i = 0; i < acc1.num_elements; i++) acc1.x[i] = gelu_exact(acc1.x[i]);
    }

    float* cp = C + (size_t)(bm + wm) * N + bn + wn;
    wmma::store_matrix_sync(cp,      acc0, N, wmma::mem_row_major);
    wmma::store_matrix_sync(cp + 16, acc1, N, wmma::mem_row_major);
}

// ---------------------------------------------------------------------------
// Window attention: one block per (window, head). 64 threads = 64 query rows.
// qkv layout: row = win*64 + t, cols = [q(384) | k(384) | v(384)], head*32+d.
// ---------------------------------------------------------------------------
__global__ __launch_bounds__(64)
void win_attn(const float* __restrict__ qkv, float* __restrict__ out)
{
    const int win  = blockIdx.x / NHEAD;
    const int head = blockIdx.x % NHEAD;
    const int t    = threadIdx.x;

    __shared__ float ks_[64][33];
    __shared__ float vs_[64][33];
    __shared__ float ls_[64][65];

    const float* rowp = qkv + (size_t)(win * 64 + t) * QKVN + head * DHEAD;

    float q[32];
    #pragma unroll
    for (int d = 0; d < 32; d++) q[d] = rowp[d];
    #pragma unroll
    for (int d = 0; d < 32; d++) ks_[t][d] = rowp[384 + d];
    #pragma unroll
    for (int d = 0; d < 32; d++) vs_[t][d] = rowp[768 + d];
    __syncthreads();

    float mx = -1e30f;
    #pragma unroll 4
    for (int j = 0; j < 64; j++) {
        float s = 0.0f;
        #pragma unroll
        for (int d = 0; d < 32; d++) s = fmaf(q[d], ks_[j][d], s);
        s *= 0.17677669529663687f;   // 1/sqrt(32)
        ls_[t][j] = s;
        mx = fmaxf(mx, s);
    }

    float sum = 0.0f;
    #pragma unroll 4
    for (int j = 0; j < 64; j++) {
        float p = __expf(ls_[t][j] - mx);
        ls_[t][j] = p;
        sum += p;
    }
    const float inv = 1.0f / sum;

    float o[32];
    #pragma unroll
    for (int d = 0; d < 32; d++) o[d] = 0.0f;
    #pragma unroll 2
    for (int j = 0; j < 64; j++) {
        const float p = ls_[t][j] * inv;
        #pragma unroll
        for (int d = 0; d < 32; d++) o[d] = fmaf(p, vs_[j][d], o[d]);
    }

    float* op = out + (size_t)(win * 64 + t) * CDIM + head * DHEAD;
    #pragma unroll
    for (int d = 0; d < 32; d++) op[d] = o[d];
}

// ---------------------------------------------------------------------------
// LayerNorm(no-bias) + residual add.  One warp per row (8 rows / 256-thr blk).
// REMAP: rows of `a` are window-ordered; residual/output are token-ordered.
// ---------------------------------------------------------------------------
template<bool REMAP>
__global__ __launch_bounds__(256)
void ln_residual(const float* __restrict__ a, const float* __restrict__ resid,
                 const float* __restrict__ gamma, float* __restrict__ out)
{
    const int row  = blockIdx.x * 8 + (threadIdx.x >> 5);
    const int lane = threadIdx.x & 31;

    int n;
    if (REMAP) {
        const int win = row >> 6, t = row & 63;
        const int b  = win >> 6;
        const int hh = ((win >> 3) & 7) * 8 + (t >> 3);
        const int w  = (win & 7) * 8 + (t & 7);
        n = (b * 64 + hh) * 64 + w;
    } else {
        n = row;
    }

    const float* ap = a + (size_t)row * CDIM;
    float v[12], s = 0.0f, ss = 0.0f;
    #pragma unroll
    for (int i = 0; i < 12; i++) {
        const float x = ap[lane + 32 * i];
        v[i] = x; s += x; ss += x * x;
    }
    #pragma unroll
    for (int o = 16; o > 0; o >>= 1) {
        s  += __shfl_xor_sync(0xFFFFFFFFu, s,  o);
        ss += __shfl_xor_sync(0xFFFFFFFFu, ss, o);
    }
    const float mu  = s * (1.0f / 384.0f);
    const float var = ss * (1.0f / 384.0f) - mu * mu;
    const float inv = rsqrtf(var + 1e-5f);

    const float* rp = resid + (size_t)n * CDIM;
    float*       op = out   + (size_t)n * CDIM;
    #pragma unroll
    for (int i = 0; i < 12; i++) {
        const int c = lane + 32 * i;
        op[c] = rp[c] + (v[i] - mu) * inv * gamma[c];
    }
}

// ---------------------------------------------------------------------------
// Launch: 7 kernels, all default stream (graph-capturable, no sync, no alloc)
// ---------------------------------------------------------------------------
extern "C" void kernel_launch(void* const* d_in, const int* in_sizes, int n_in,
                              void* d_out, int out_size)
{
    const float* x          = (const float*)d_in[0];
    const float* w_qkv      = (const float*)d_in[1];
    const float* w_out      = (const float*)d_in[2];
    const float* gamma_attn = (const float*)d_in[3];
    const float* w1         = (const float*)d_in[4];
    const float* w2         = (const float*)d_in[5];
    const float* gamma_ff   = (const float*)d_in[6];
    float*       out        = (float*)d_out;

    float *qkv, *attn, *proj, *y, *h, *f;
    cudaGetSymbolAddress((void**)&qkv,  g_qkv);
    cudaGetSymbolAddress((void**)&attn, g_attn);
    cudaGetSymbolAddress((void**)&proj, g_proj);
    cudaGetSymbolAddress((void**)&y,    g_y);
    cudaGetSymbolAddress((void**)&h,    g_h);
    cudaGetSymbolAddress((void**)&f,    g_f);

    // 1) qkv = shift2d(x) @ w_qkv           (window-ordered rows)
    gemm_tf32<true, false><<<dim3(QKVN / BN, NTOK / BM), 256>>>(x, w_qkv, qkv, NTOK, QKVN, CDIM);
    // 2) attention per (window, head)
    win_attn<<<NWIN * NHEAD, 64>>>(qkv, attn);
    // 3) proj = attn @ w_out                (window-ordered rows)
    gemm_tf32<false, false><<<dim3(CDIM / BN, NTOK / BM), 256>>>(attn, w_out, proj, NTOK, CDIM, CDIM);
    // 4) y = x + LN(proj) * gamma_attn      (remap window rows -> tokens)
    ln_residual<true><<<NTOK / 8, 256>>>(proj, x, gamma_attn, y);
    // 5) h = gelu(y @ w1)
    gemm_tf32<false, true><<<dim3(DFFN / BN, NTOK / BM), 256>>>(y, w1, h, NTOK, DFFN, CDIM);
    // 6) f = h @ w2
    gemm_tf32<false, false><<<dim3(CDIM / BN, NTOK / BM), 256>>>(h, w2, f, NTOK, CDIM, DFFN);
    // 7) out = y + LN(f) * gamma_ff
    ln_residual<false><<<NTOK / 8, 256>>>(f, y, gamma_ff, out);
}

// round 3
// speedup vs baseline: 1.2415x; 1.2415x over previous
#include <cuda_runtime.h>
#include <cuda_bf16.h>
#include <mma.h>
#include <cstdint>
#include <cstddef>

using namespace nvcuda;

// ---------------------------------------------------------------------------
// Problem dims (fixed by the reference)
// ---------------------------------------------------------------------------
#define NTOK   65536          // B*H*W = 16*64*64
#define CDIM   384
#define QKVN   1152           // 3*NH*DH
#define DFFN   1536
#define NHEAD  12
#define DHEAD  32
#define NWIN   1024           // B * 8 * 8

// ---------------------------------------------------------------------------
// Scratch (static device globals -- no allocation allowed)
// ---------------------------------------------------------------------------
__device__ __align__(256) float g_qkv [(size_t)NTOK * QKVN];   // window-row order
__device__ __align__(256) float g_attn[(size_t)NTOK * CDIM];   // window-row order
__device__ __align__(256) float g_proj[(size_t)NTOK * CDIM];   // window-row order
__device__ __align__(256) float g_y   [(size_t)NTOK * CDIM];   // token order
__device__ __align__(256) float g_h   [(size_t)NTOK * DFFN];   // FFN hidden
__device__ __align__(256) float g_f   [(size_t)NTOK * CDIM];   // FFN out (pre-LN)

// ---------------------------------------------------------------------------
// Pipelined TF32 wmma GEMM, C = A @ B (all row-major), fp32 accumulate.
// Block tile 128x128, K-tile 32, 3-stage cp.async pipeline.
// 8 warps in a 2x4 grid; each warp computes 64x32 (4x2 fragments of 16x16).
// SHIFT_A: A rows are window-ordered tokens of shift2d(x), gathered on the fly
//          (16B chunks never straddle a 96-channel quarter; border rows are
//          zero-filled via cp.async src-size 0).
// GELU:    exact gelu applied to accumulators before store.
// ---------------------------------------------------------------------------
constexpr int BM = 128, BN = 128, BK = 32;
constexpr int STAGES = 3;
constexpr int ALD = BK + 4;   // 36 floats (rows stay 16B aligned: 144B)
constexpr int BLD = BN + 4;   // 132 floats (528B, 16B aligned)
constexpr int A_STAGE = BM * ALD;           // 4608 floats
constexpr int B_STAGE = BK * BLD;           // 4224 floats
constexpr size_t GEMM_SMEM = (size_t)STAGES * (A_STAGE + B_STAGE) * 4;  // 105984 B

__device__ __forceinline__ float gelu_exact(float v) {
    return 0.5f * v * (1.0f + erff(v * 0.7071067811865475f));
}

__device__ __forceinline__ void cpa16(uint32_t dst, const void* src) {
    asm volatile("cp.async.cg.shared.global [%0], [%1], 16;\n" :: "r"(dst), "l"(src));
}
__device__ __forceinline__ void cpa16_pred(uint32_t dst, const void* src, bool valid) {
    int sz = valid ? 16 : 0;   // src-size 0 => zero-fill, src not dereferenced
    asm volatile("cp.async.cg.shared.global [%0], [%1], 16, %2;\n"
                 :: "r"(dst), "l"(src), "r"(sz));
}
__device__ __forceinline__ void cpa_commit() {
    asm volatile("cp.async.commit_group;\n");
}
template<int N> __device__ __forceinline__ void cpa_wait() {
    asm volatile("cp.async.wait_group %0;\n" :: "n"(N));
}

template<bool SHIFT_A, bool GELU>
__global__ __launch_bounds__(256)
void gemm_pipe(const float* __restrict__ A, const float* __restrict__ B,
               float* __restrict__ C, int M, int N, int K)
{
    extern __shared__ float smem[];
    float* As = smem;                          // [STAGES][BM][ALD]
    float* Bs = smem + STAGES * A_STAGE;       // [STAGES][BK][BLD]

    const int bm   = blockIdx.y * BM;
    const int bn   = blockIdx.x * BN;
    const int tid  = threadIdx.x;
    const int warp = tid >> 5;
    const int wrow = (warp >> 2) * 64;         // 0 or 64
    const int wcol = (warp & 3) * 32;          // 0,32,64,96

    // ---- loader decomposition: 4 float4 per thread for A and for B --------
    // A: 128 rows x 8 float4/row  (idx = tid + 256j; row = idx>>3, c4 = idx&7)
    // B:  32 rows x 32 float4/row (idx = tid + 256j; row = idx>>5, c4 = idx&31)
    int a_row[4], a_col[4];
    int b_row[4], b_col[4];
    int bb[4], hy[4], wx[4];                   // shift gather metadata per A row
    #pragma unroll
    for (int j = 0; j < 4; j++) {
        const int idx = tid + 256 * j;
        a_row[j] = idx >> 3;
        a_col[j] = (idx & 7) * 4;
        b_row[j] = idx >> 5;
        b_col[j] = (idx & 31) * 4;
        if (SHIFT_A) {
            const int grow = bm + a_row[j];
            const int win  = grow >> 6;
            const int t    = grow & 63;
            bb[j] = win >> 6;
            hy[j] = ((win >> 3) & 7) * 8 + (t >> 3);
            wx[j] = (win & 7) * 8 + (t & 7);
        }
    }

    const int nk = K / BK;

    auto load_tile = [&](int kt, int stage) {
        const int kbase = kt * BK;
        float* as = As + stage * A_STAGE;
        float* bs = Bs + stage * B_STAGE;
        #pragma unroll
        for (int j = 0; j < 4; j++) {
            const uint32_t dst =
                (uint32_t)__cvta_generic_to_shared(as + a_row[j] * ALD + a_col[j]);
            if (SHIFT_A) {
                const int kk  = kbase + a_col[j];
                const int qtr = kk / 96;
                int sh = hy[j], sw = wx[j];
                bool valid;
                if      (qtr == 0) { sh = hy[j] - 1; valid = (sh >= 0); }
                else if (qtr == 1) { sh = hy[j] + 1; valid = (sh < 64); }
                else if (qtr == 2) { sw = wx[j] - 1; valid = (sw >= 0); }
                else               { sw = wx[j] + 1; valid = (sw < 64); }
                const float* sp = A + (size_t)((bb[j] * 64 + sh) * 64 + sw) * CDIM + kk;
                cpa16_pred(dst, sp, valid);
            } else {
                cpa16(dst, A + (size_t)(bm + a_row[j]) * K + kbase + a_col[j]);
            }
        }
        #pragma unroll
        for (int j = 0; j < 4; j++) {
            const uint32_t dst =
                (uint32_t)__cvta_generic_to_shared(bs + b_row[j] * BLD + b_col[j]);
            cpa16(dst, B + (size_t)(kbase + b_row[j]) * N + bn + b_col[j]);
        }
    };

    // ---- accumulators ------------------------------------------------------
    wmma::fragment<wmma::accumulator, 16, 16, 8, float> acc[4][2];
    #pragma unroll
    for (int i = 0; i < 4; i++)
        #pragma unroll
        for (int j = 0; j < 2; j++)
            wmma::fill_fragment(acc[i][j], 0.0f);

    // ---- prologue: stages 0..STAGES-2 --------------------------------------
    #pragma unroll
    for (int s = 0; s < STAGES - 1; s++) {
        load_tile(s, s);
        cpa_commit();
    }

    // ---- mainloop -----------------------------------------------------------
    for (int kt = 0; kt < nk; kt++) {
        cpa_wait<STAGES - 2>();
        __syncthreads();

        const int pf = kt + STAGES - 1;
        if (pf < nk) load_tile(pf, pf % STAGES);
        cpa_commit();

        const float* as = As + (kt % STAGES) * A_STAGE;
        const float* bs = Bs + (kt % STAGES) * B_STAGE;

        #pragma unroll
        for (int ks = 0; ks < BK; ks += 8) {
            wmma::fragment<wmma::matrix_a, 16, 16, 8, wmma::precision::tf32, wmma::row_major> af[4];
            #pragma unroll
            for (int i = 0; i < 4; i++) {
                wmma::load_matrix_sync(af[i], as + (wrow + i * 16) * ALD + ks, ALD);
                #pragma unroll
                for (int e = 0; e < af[i].num_elements; e++)
                    af[i].x[e] = wmma::__float_to_tf32(af[i].x[e]);
            }
            wmma::fragment<wmma::matrix_b, 16, 16, 8, wmma::precision::tf32, wmma::row_major> bf[2];
            #pragma unroll
            for (int j = 0; j < 2; j++) {
                wmma::load_matrix_sync(bf[j], bs + ks * BLD + wcol + j * 16, BLD);
                #pragma unroll
                for (int e = 0; e < bf[j].num_elements; e++)
                    bf[j].x[e] = wmma::__float_to_tf32(bf[j].x[e]);
            }
            #pragma unroll
            for (int i = 0; i < 4; i++)
                #pragma unroll
                for (int j = 0; j < 2; j++)
                    wmma::mma_sync(acc[i][j], af[i], bf[j], acc[i][j]);
        }
        __syncthreads();
    }

    // ---- epilogue -----------------------------------------------------------
    #pragma unroll
    for (int i = 0; i < 4; i++)
        #pragma unroll
        for (int j = 0; j < 2; j++) {
            if (GELU) {
                #pragma unroll
                for (int e = 0; e < acc[i][j].num_elements; e++)
                    acc[i][j].x[e] = gelu_exact(acc[i][j].x[e]);
            }
            wmma::store_matrix_sync(
                C + (size_t)(bm + wrow + i * 16) * N + bn + wcol + j * 16,
                acc[i][j], N, wmma::mem_row_major);
        }
}

// ---------------------------------------------------------------------------
// Window attention: one block per (window, head). 64 threads = 64 query rows.
// qkv layout: row = win*64 + t, cols = [q(384) | k(384) | v(384)], head*32+d.
// ---------------------------------------------------------------------------
__global__ __launch_bounds__(64)
void win_attn(const float* __restrict__ qkv, float* __restrict__ out)
{
    const int win  = blockIdx.x / NHEAD;
    const int head = blockIdx.x % NHEAD;
    const int t    = threadIdx.x;

    __shared__ float ks_[64][33];
    __shared__ float vs_[64][33];
    __shared__ float ls_[64][65];

    const float* rowp = qkv + (size_t)(win * 64 + t) * QKVN + head * DHEAD;

    float q[32];
    #pragma unroll
    for (int d = 0; d < 32; d++) q[d] = rowp[d];
    #pragma unroll
    for (int d = 0; d < 32; d++) ks_[t][d] = rowp[384 + d];
    #pragma unroll
    for (int d = 0; d < 32; d++) vs_[t][d] = rowp[768 + d];
    __syncthreads();

    float mx = -1e30f;
    #pragma unroll 4
    for (int j = 0; j < 64; j++) {
        float s = 0.0f;
        #pragma unroll
        for (int d = 0; d < 32; d++) s = fmaf(q[d], ks_[j][d], s);
        s *= 0.17677669529663687f;   // 1/sqrt(32)
        ls_[t][j] = s;
        mx = fmaxf(mx, s);
    }

    float sum = 0.0f;
    #pragma unroll 4
    for (int j = 0; j < 64; j++) {
        float p = __expf(ls_[t][j] - mx);
        ls_[t][j] = p;
        sum += p;
    }
    const float inv = 1.0f / sum;

    float o[32];
    #pragma unroll
    for (int d = 0; d < 32; d++) o[d] = 0.0f;
    #pragma unroll 2
    for (int j = 0; j < 64; j++) {
        const float p = ls_[t][j] * inv;
        #pragma unroll
        for (int d = 0; d < 32; d++) o[d] = fmaf(p, vs_[j][d], o[d]);
    }

    float* op = out + (size_t)(win * 64 + t) * CDIM + head * DHEAD;
    #pragma unroll
    for (int d = 0; d < 32; d++) op[d] = o[d];
}

// ---------------------------------------------------------------------------
// LayerNorm(no-bias) + residual add.  One warp per row (8 rows / 256-thr blk).
// REMAP: rows of `a` are window-ordered; residual/output are token-ordered.
// ---------------------------------------------------------------------------
template<bool REMAP>
__global__ __launch_bounds__(256)
void ln_residual(const float* __restrict__ a, const float* __restrict__ resid,
                 const float* __restrict__ gamma, float* __restrict__ out)
{
    const int row  = blockIdx.x * 8 + (threadIdx.x >> 5);
    const int lane = threadIdx.x & 31;

    int n;
    if (REMAP) {
        const int win = row >> 6, t = row & 63;
        const int b  = win >> 6;
        const int hh = ((win >> 3) & 7) * 8 + (t >> 3);
        const int w  = (win & 7) * 8 + (t & 7);
        n = (b * 64 + hh) * 64 + w;
    } else {
        n = row;
    }

    const float* ap = a + (size_t)row * CDIM;
    float v[12], s = 0.0f, ss = 0.0f;
    #pragma unroll
    for (int i = 0; i < 12; i++) {
        const float x = ap[lane + 32 * i];
        v[i] = x; s += x; ss += x * x;
    }
    #pragma unroll
    for (int o = 16; o > 0; o >>= 1) {
        s  += __shfl_xor_sync(0xFFFFFFFFu, s,  o);
        ss += __shfl_xor_sync(0xFFFFFFFFu, ss, o);
    }
    const float mu  = s * (1.0f / 384.0f);
    const float var = ss * (1.0f / 384.0f) - mu * mu;
    const float inv = rsqrtf(var + 1e-5f);

    const float* rp = resid + (size_t)n * CDIM;
    float*       op = out   + (size_t)n * CDIM;
    #pragma unroll
    for (int i = 0; i < 12; i++) {
        const int c = lane + 32 * i;
        op[c] = rp[c] + (v[i] - mu) * inv * gamma[c];
    }
}

// ---------------------------------------------------------------------------
// Launch: 7 kernels, all default stream (graph-capturable, no sync, no alloc)
// ---------------------------------------------------------------------------
extern "C" void kernel_launch(void* const* d_in, const int* in_sizes, int n_in,
                              void* d_out, int out_size)
{
    const float* x          = (const float*)d_in[0];
    const float* w_qkv      = (const float*)d_in[1];
    const float* w_out      = (const float*)d_in[2];
    const float* gamma_attn = (const float*)d_in[3];
    const float* w1         = (const float*)d_in[4];
    const float* w2         = (const float*)d_in[5];
    const float* gamma_ff   = (const float*)d_in[6];
    float*       out        = (float*)d_out;

    float *qkv, *attn, *proj, *y, *h, *f;
    cudaGetSymbolAddress((void**)&qkv,  g_qkv);
    cudaGetSymbolAddress((void**)&attn, g_attn);
    cudaGetSymbolAddress((void**)&proj, g_proj);
    cudaGetSymbolAddress((void**)&y,    g_y);
    cudaGetSymbolAddress((void**)&h,    g_h);
    cudaGetSymbolAddress((void**)&f,    g_f);

    cudaFuncSetAttribute(gemm_pipe<true,  false>,
                         cudaFuncAttributeMaxDynamicSharedMemorySize, (int)GEMM_SMEM);
    cudaFuncSetAttribute(gemm_pipe<false, false>,
                         cudaFuncAttributeMaxDynamicSharedMemorySize, (int)GEMM_SMEM);
    cudaFuncSetAttribute(gemm_pipe<false, true>,
                         cudaFuncAttributeMaxDynamicSharedMemorySize, (int)GEMM_SMEM);

    // 1) qkv = shift2d(x) @ w_qkv           (window-ordered rows)
    gemm_pipe<true, false><<<dim3(QKVN / BN, NTOK / BM), 256, GEMM_SMEM>>>
        (x, w_qkv, qkv, NTOK, QKVN, CDIM);
    // 2) attention per (window, head)
    win_attn<<<NWIN * NHEAD, 64>>>(qkv, attn);
    // 3) proj = attn @ w_out                (window-ordered rows)
    gemm_pipe<false, false><<<dim3(CDIM / BN, NTOK / BM), 256, GEMM_SMEM>>>
        (attn, w_out, proj, NTOK, CDIM, CDIM);
    // 4) y = x + LN(proj) * gamma_attn      (remap window rows -> tokens)
    ln_residual<true><<<NTOK / 8, 256>>>(proj, x, gamma_attn, y);
    // 5) h = gelu(y @ w1)
    gemm_pipe<false, true><<<dim3(DFFN / BN, NTOK / BM), 256, GEMM_SMEM>>>
        (y, w1, h, NTOK, DFFN, CDIM);
    // 6) f = h @ w2
    gemm_pipe<false, false><<<dim3(CDIM / BN, NTOK / BM), 256, GEMM_SMEM>>>
        (h, w2, f, NTOK, CDIM, DFFN);
    // 7) out = y + LN(f) * gamma_ff
    ln_residual<false><<<NTOK / 8, 256>>>(f, y, gamma_ff, out);
}